// round 12
// baseline (speedup 1.0000x reference)
#include <cuda_runtime.h>
#include <cuda_fp16.h>
#include <stdint.h>

static constexpr int SEQ  = 2048;
static constexpr int VOC  = 50257;
static constexpr int EMB  = 768;
static constexpr int KPAD = 50304;   // VOC padded to multiple of 64 (K of QKV gemm)
static constexpr int NPAD = 50304;   // VOC padded to multiple of 128 (N of out gemm)

#define BM 128
#define BN 128
#define BK 64
#define STAGES 3
#define THREADS 256
#define A_STRIDE 72                       // 64+8 halfs -> 144B rows, ldsm conflict-free
#define BNT_STRIDE 136                    // non-BT wide B rows: 128+8 halfs
#define BNT_STRIDE_N 72                   // non-BT narrow B rows: 64+8 halfs
#define A_HALF_PER_STAGE (BM * A_STRIDE)  // 9216
#define B_HALF_WIDE (BM * A_STRIDE)       // 9216 (>= 64*136 = 8704)
#define B_HALF_NARROW (64 * BNT_STRIDE_N) // 4608
#define SMEM_BYTES  (STAGES * (A_HALF_PER_STAGE + B_HALF_WIDE) * 2)     // 110592
#define SMEM_BYTES_N (STAGES * (A_HALF_PER_STAGE + B_HALF_NARROW) * 2)  // 82944

// ---------------- scratch (__device__ globals; no allocation allowed) ---------
__device__ __half g_Wqh[(size_t)KPAD * EMB];
__device__ __half g_Wkh[(size_t)KPAD * EMB];
__device__ __half g_Wvh[(size_t)KPAD * EMB];
__device__ __half g_Woh[(size_t)EMB * NPAD];
__device__ __half g_Q[SEQ * EMB];
__device__ __half g_Km[SEQ * EMB];
__device__ __half g_V[SEQ * EMB];
__device__ __half g_attn[(size_t)SEQ * SEQ];   // exp(scores), unnormalized
__device__ float  g_rowsum[SEQ];
__device__ __half g_ctx[SEQ * EMB];

// ---------------- helpers ----------------------------------------------------
__device__ __forceinline__ void cp_async16(uint32_t dst, const void* src) {
    asm volatile("cp.async.cg.shared.global [%0], [%1], 16;\n" :: "r"(dst), "l"(src));
}
__device__ __forceinline__ void cp_commit() {
    asm volatile("cp.async.commit_group;\n");
}
__device__ __forceinline__ void cp_wait() {
    asm volatile("cp.async.wait_group %0;\n" :: "n"(STAGES - 2));
}
__device__ __forceinline__ void ldsm_x4(uint32_t* r, uint32_t addr) {
    asm volatile("ldmatrix.sync.aligned.m8n8.x4.shared.b16 {%0,%1,%2,%3}, [%4];\n"
                 : "=r"(r[0]), "=r"(r[1]), "=r"(r[2]), "=r"(r[3]) : "r"(addr));
}
__device__ __forceinline__ void ldsm_x4_t(uint32_t* r, uint32_t addr) {
    asm volatile("ldmatrix.sync.aligned.m8n8.x4.trans.shared.b16 {%0,%1,%2,%3}, [%4];\n"
                 : "=r"(r[0]), "=r"(r[1]), "=r"(r[2]), "=r"(r[3]) : "r"(addr));
}
__device__ __forceinline__ void mma16816(float* c, const uint32_t* a, const uint32_t* b) {
    asm volatile(
        "mma.sync.aligned.m16n8k16.row.col.f32.f16.f16.f32 "
        "{%0,%1,%2,%3}, {%4,%5,%6,%7}, {%8,%9}, {%0,%1,%2,%3};\n"
        : "+f"(c[0]), "+f"(c[1]), "+f"(c[2]), "+f"(c[3])
        : "r"(a[0]), "r"(a[1]), "r"(a[2]), "r"(a[3]), "r"(b[0]), "r"(b[1]));
}
// Fast exp on the FMA pipe (no MUFU); valid for |score| within clamp range.
__device__ __forceinline__ float fast_exp(float x) {
    float y = x * 1.4426950408889634f;
    y = fminf(fmaxf(y, -100.0f), 15.5f);
    const float t = y + 12582912.0f;      // 1.5 * 2^23
    const float nf = t - 12582912.0f;
    const float f = y - nf;
    const int n = (int)nf;
    float p = 0.00133335581f;
    p = fmaf(p, f, 0.00961812910f);
    p = fmaf(p, f, 0.0555041086f);
    p = fmaf(p, f, 0.240226507f);
    p = fmaf(p, f, 0.693147182f);
    p = fmaf(p, f, 1.0f);
    return p * __int_as_float((n + 127) << 23);
}

// ---------------- conversion kernels -----------------------------------------
__global__ __launch_bounds__(256) void cvt_pad2d(const float* __restrict__ s,
                                                 __half2* __restrict__ d,
                                                 int srcW, int dstW2) {
    const int c2 = blockIdx.x * 256 + threadIdx.x;
    const size_t row = blockIdx.y;
    if (c2 < dstW2) {
        const int col = c2 * 2;
        const float* sr = s + row * (size_t)srcW;
        const float v0 = (col < srcW) ? sr[col] : 0.f;
        const float v1 = (col + 1 < srcW) ? sr[col + 1] : 0.f;
        d[row * (size_t)dstW2 + c2] = __floats2half2_rn(v0, v1);
    }
}
__global__ __launch_bounds__(256) void cvt_tail4(const float4* __restrict__ s,
                                                 uint2* __restrict__ d,
                                                 long nValid4, long nTotal4) {
    long i = (long)blockIdx.x * blockDim.x + threadIdx.x;
    const long stride = (long)gridDim.x * blockDim.x;
    for (; i < nTotal4; i += stride) {
        float4 v = (i < nValid4) ? s[i] : make_float4(0.f, 0.f, 0.f, 0.f);
        __half2 lo = __floats2half2_rn(v.x, v.y);
        __half2 hi = __floats2half2_rn(v.z, v.w);
        uint2 o;
        o.x = *(const uint32_t*)&lo;
        o.y = *(const uint32_t*)&hi;
        d[i] = o;
    }
}

// ---------------- pipelined fp16 GEMM (BK=64, 3 stages, 2 CTA/SM) -------------
// C[M,N] = A[M,K] @ B (+bias)*alpha.  B row-major [K,N] if !BT, [N,K] if BT.
// NARROW: BN=64.  EXPOUT: write fp16 exp(acc).  NORM: 1/rowsum in epilogue.
// AF32: A is raw fp32 (row stride lda, valid width lda); producer converts
//       fp32->fp16 in-kernel (LDG staged one tile ahead + STS).
// GRIDT: blockIdx.x = row-block, blockIdx.y = col-block (L2-friendly for out).
template <bool BT, bool OUT_HALF, bool HAS_BIAS, bool FUSED3, bool NARROW,
          bool EXPOUT, bool NORM, bool AF32, bool GRIDT>
__global__ __launch_bounds__(THREADS, 2) void gemm2(
    const __half* __restrict__ A, const float* __restrict__ Afp,
    const __half* __restrict__ B0, const __half* __restrict__ B1, const __half* __restrict__ B2,
    const float* __restrict__ bias0, const float* __restrict__ bias1, const float* __restrict__ bias2,
    float* __restrict__ Cf,
    __half* __restrict__ Ch0, __half* __restrict__ Ch1, __half* __restrict__ Ch2,
    const float* __restrict__ rowsum,
    int M, int N, int K, int lda, int ldb, int ldc, float alpha)
{
    constexpr int BN_E = NARROW ? 64 : 128;
    constexpr int MI = NARROW ? 2 : 4;
    constexpr int B_HALF_STG = NARROW ? B_HALF_NARROW : B_HALF_WIDE;
    constexpr int BS_NT = NARROW ? BNT_STRIDE_N : BNT_STRIDE;

    extern __shared__ __half sm[];
    __half* As = sm;
    __half* Bs = sm + STAGES * A_HALF_PER_STAGE;

    const int tid = threadIdx.x;
    const int row0 = (GRIDT ? blockIdx.x : blockIdx.y) * BM;

    const __half* B = B0;
    const float* bias = bias0;
    __half* Ch = Ch0;
    float aScale = alpha;
    int col0;
    if constexpr (FUSED3) {
        const int blocksPer = N / BN_E;
        const int sel = blockIdx.x / blocksPer;
        col0 = (blockIdx.x % blocksPer) * BN_E;
        if (sel == 1) { B = B1; bias = bias1; Ch = Ch1; aScale = 1.f; }
        else if (sel == 2) { B = B2; bias = bias2; Ch = Ch2; aScale = 1.f; }
    } else {
        col0 = (GRIDT ? blockIdx.y : blockIdx.x) * BN_E;
    }

    const uint32_t smA = (uint32_t)__cvta_generic_to_shared(As);
    const uint32_t smB = (uint32_t)__cvta_generic_to_shared(Bs);

    const int nTiles = K / BK;

    // ---- AF32 A-producer state: 32 fp32 staged one tile ahead ----
    float staged[AF32 ? 32 : 1];
    const int arow = tid >> 3;             // base row (h adds 32)
    const int akcu = (tid & 7) * 8;        // k offset within tile (h-invariant)
    const float* Athr = AF32 ? (Afp + (size_t)(row0 + arow) * lda + akcu) : nullptr;

    auto ldgA = [&](int t) {
        const int k0 = t * BK;
        const int rem = lda - (k0 + akcu);   // lda == valid fp32 width (VOC)
#pragma unroll
        for (int h = 0; h < 4; h++) {
            const float* src = Athr + (size_t)h * 32 * lda + k0;
#pragma unroll
            for (int j = 0; j < 8; j++)
                staged[h * 8 + j] = (j < rem) ? src[j] : 0.f;
        }
    };
    auto stsA = [&](int slot) {
#pragma unroll
        for (int h = 0; h < 4; h++) {
            uint32_t p[4];
#pragma unroll
            for (int q = 0; q < 4; q++) {
                __half2 hv = __floats2half2_rn(staged[h * 8 + q * 2], staged[h * 8 + q * 2 + 1]);
                p[q] = *(uint32_t*)&hv;
            }
            __half* dst = As + slot * A_HALF_PER_STAGE + (arow + h * 32) * A_STRIDE + akcu;
            *(uint2*)(dst) = make_uint2(p[0], p[1]);
            *(uint2*)(dst + 4) = make_uint2(p[2], p[3]);
        }
    };

    auto loadStage = [&](int t, int slot) {
        const int k0 = t * BK;
        if constexpr (!AF32) {
#pragma unroll
            for (int h = 0; h < 4; h++) {
                const int c = tid + h * 256;
                const int row = c >> 3, kc = (c & 7) * 8;
                const uint32_t dst = smA + (uint32_t)(slot * A_HALF_PER_STAGE + row * A_STRIDE + kc) * 2;
                cp_async16(dst, A + (size_t)(row0 + row) * lda + (k0 + kc));
            }
        }
        if constexpr (BT) {
#pragma unroll
            for (int h = 0; h < 4; h++) {
                const int c = tid + h * 256;
                const int nr = c >> 3, kc = (c & 7) * 8;
                const uint32_t dst = smB + (uint32_t)(slot * B_HALF_STG + nr * A_STRIDE + kc) * 2;
                cp_async16(dst, B + (size_t)(col0 + nr) * ldb + (k0 + kc));
            }
        } else if constexpr (NARROW) {
#pragma unroll
            for (int h = 0; h < 2; h++) {
                const int c = tid + h * 256;
                const int kr = c >> 3, nc = (c & 7) * 8;
                const uint32_t dst = smB + (uint32_t)(slot * B_HALF_STG + kr * BS_NT + nc) * 2;
                cp_async16(dst, B + (size_t)(k0 + kr) * ldb + (col0 + nc));
            }
        } else {
#pragma unroll
            for (int h = 0; h < 4; h++) {
                const int c = tid + h * 256;
                const int kr = c >> 4, nc = (c & 15) * 8;
                const uint32_t dst = smB + (uint32_t)(slot * B_HALF_STG + kr * BS_NT + nc) * 2;
                cp_async16(dst, B + (size_t)(k0 + kr) * ldb + (col0 + nc));
            }
        }
    };

    const int warp = tid >> 5, lane = tid & 31;
    const int wm = NARROW ? (warp & 3) * 32 : (warp & 1) * 64;
    const int wn = NARROW ? (warp >> 2) * 32 : (warp >> 1) * 32;
    const int g = lane >> 2, t4 = lane & 3;
    const int lrow = lane & 15;
    const int lcol8 = (lane >> 4) << 3;
    const int mrow = lane & 7;
    const int msel = lane >> 3;

    float acc[MI][4][4];
#pragma unroll
    for (int mi = 0; mi < MI; mi++)
#pragma unroll
        for (int ni = 0; ni < 4; ni++)
#pragma unroll
            for (int q = 0; q < 4; q++) acc[mi][ni][q] = 0.f;

    // prologue
    if constexpr (AF32) {
        ldgA(0); loadStage(0, 0); cp_commit();
        stsA(0);
        ldgA(1); loadStage(1, 1); cp_commit();
    } else {
#pragma unroll
        for (int s = 0; s < STAGES - 1; s++) {
            loadStage(s, s);
            cp_commit();
        }
    }

    for (int t = 0; t < nTiles; t++) {
        cp_wait();
        __syncthreads();

        const int slot = t % STAGES;
        const uint32_t aBase = smA + (uint32_t)(slot * A_HALF_PER_STAGE) * 2;
        const uint32_t bBase = smB + (uint32_t)(slot * B_HALF_STG) * 2;

        auto computeK = [&](int ks) {
            uint32_t a[MI][4];
#pragma unroll
            for (int mi = 0; mi < MI; mi++) {
                const uint32_t addr = aBase + (uint32_t)((wm + mi * 16 + lrow) * A_STRIDE + ks + lcol8) * 2;
                ldsm_x4(a[mi], addr);
            }
            uint32_t b[4][2];
            if constexpr (BT) {
#pragma unroll
                for (int nj = 0; nj < 2; nj++) {
                    uint32_t r[4];
                    const int n = wn + nj * 16 + ((msel >> 1) << 3) + mrow;
                    const int kk = ks + ((msel & 1) << 3);
                    ldsm_x4(r, bBase + (uint32_t)(n * A_STRIDE + kk) * 2);
                    b[nj * 2][0] = r[0]; b[nj * 2][1] = r[1];
                    b[nj * 2 + 1][0] = r[2]; b[nj * 2 + 1][1] = r[3];
                }
            } else {
#pragma unroll
                for (int nj = 0; nj < 2; nj++) {
                    uint32_t r[4];
                    const uint32_t addr = bBase + (uint32_t)((ks + lrow) * BS_NT + wn + nj * 16 + lcol8) * 2;
                    ldsm_x4_t(r, addr);
                    b[nj * 2][0] = r[0]; b[nj * 2][1] = r[1];
                    b[nj * 2 + 1][0] = r[2]; b[nj * 2 + 1][1] = r[3];
                }
            }
#pragma unroll
            for (int mi = 0; mi < MI; mi++)
#pragma unroll
                for (int ni = 0; ni < 4; ni++)
                    mma16816(acc[mi][ni], a[mi], b[ni]);
        };

        computeK(0);

        if constexpr (AF32) {
            if (t + 1 < nTiles) stsA((t + 1) % STAGES);   // A data loaded last tile
        }
        const int nt = t + STAGES - 1;
        if (nt < nTiles) {
            if constexpr (AF32) ldgA(nt);
            loadStage(nt, nt % STAGES);
        }
        cp_commit();

        computeK(16);
        computeK(32);
        computeK(48);
    }

    // ---------------- epilogue ----------------
    float invr[MI][2];
    if constexpr (NORM) {
#pragma unroll
        for (int mi = 0; mi < MI; mi++)
#pragma unroll
            for (int hr = 0; hr < 2; hr++)
                invr[mi][hr] = 1.0f / rowsum[row0 + wm + mi * 16 + g + hr * 8];
    }

#pragma unroll
    for (int mi = 0; mi < MI; mi++) {
#pragma unroll
        for (int ni = 0; ni < 4; ni++) {
            const int r = row0 + wm + mi * 16 + g;
            const int cn = col0 + wn + ni * 8 + t4 * 2;
            if constexpr (EXPOUT) {
#pragma unroll
                for (int hr = 0; hr < 2; hr++) {
                    const int rr = r + hr * 8;
                    const float e0 = fast_exp(acc[mi][ni][hr * 2]);
                    const float e1 = fast_exp(acc[mi][ni][hr * 2 + 1]);
                    *(__half2*)(Ch + (size_t)rr * ldc + cn) = __floats2half2_rn(e0, e1);
                }
            } else if constexpr (OUT_HALF) {
#pragma unroll
                for (int hr = 0; hr < 2; hr++) {
                    const int rr = r + hr * 8;
                    float v0 = acc[mi][ni][hr * 2];
                    float v1 = acc[mi][ni][hr * 2 + 1];
                    if constexpr (HAS_BIAS) { v0 += bias[cn]; v1 += bias[cn + 1]; }
                    if constexpr (NORM) { v0 *= invr[mi][hr]; v1 *= invr[mi][hr]; }
                    else                { v0 *= aScale;       v1 *= aScale; }
                    *(__half2*)(Ch + (size_t)rr * ldc + cn) = __floats2half2_rn(v0, v1);
                }
            } else {
#pragma unroll
                for (int q = 0; q < 4; q++) {
                    const int rr = r + (q >> 1) * 8;
                    const int cc = cn + (q & 1);
                    if (cc < N) {
                        float bv = 0.f;
                        if constexpr (HAS_BIAS) bv = bias[cc];
                        Cf[(size_t)rr * ldc + cc] = (acc[mi][ni][q] + bv) * aScale;
                    }
                }
            }
        }
    }
}

// ---------------- row-sum of exp-scores (deterministic) -----------------------
__global__ __launch_bounds__(256) void rowsum_kernel(
    const __half2* __restrict__ E_, float* __restrict__ rs)
{
    __shared__ float red[8];
    const int row = blockIdx.x;
    const __half2* e = E_ + (size_t)row * (SEQ / 2);
    const int tid = threadIdx.x;

    float s = 0.f;
#pragma unroll
    for (int j = 0; j < 4; j++) {
        const float2 v = __half22float2(e[tid + j * 256]);
        s += v.x + v.y;
    }
#pragma unroll
    for (int o = 16; o; o >>= 1) s += __shfl_xor_sync(0xffffffffu, s, o);
    if ((tid & 31) == 0) red[tid >> 5] = s;
    __syncthreads();
    if (tid == 0) {
        float tot = 0.f;
#pragma unroll
        for (int i = 0; i < 8; i++) tot += red[i];
        rs[row] = tot;
    }
}

// ---------------- launch ------------------------------------------------------
extern "C" void kernel_launch(void* const* d_in, const int* in_sizes, int n_in,
                              void* d_out, int out_size)
{
    const float* x  = (const float*)d_in[0];
    const float* Wq = (const float*)d_in[1];
    const float* bq = (const float*)d_in[2];
    const float* Wk = (const float*)d_in[3];
    const float* bk = (const float*)d_in[4];
    const float* Wv = (const float*)d_in[5];
    const float* bv = (const float*)d_in[6];
    const float* Wo = (const float*)d_in[7];
    const float* bo = (const float*)d_in[8];
    float* out = (float*)d_out;

    __half *pWqh, *pWkh, *pWvh, *pWoh, *pQ, *pK, *pV, *pAttn, *pCtx;
    float* pRS;
    cudaGetSymbolAddress((void**)&pWqh, g_Wqh);
    cudaGetSymbolAddress((void**)&pWkh, g_Wkh);
    cudaGetSymbolAddress((void**)&pWvh, g_Wvh);
    cudaGetSymbolAddress((void**)&pWoh, g_Woh);
    cudaGetSymbolAddress((void**)&pQ, g_Q);
    cudaGetSymbolAddress((void**)&pK, g_Km);
    cudaGetSymbolAddress((void**)&pV, g_V);
    cudaGetSymbolAddress((void**)&pAttn, g_attn);
    cudaGetSymbolAddress((void**)&pRS, g_rowsum);
    cudaGetSymbolAddress((void**)&pCtx, g_ctx);

    // kernel variants
    auto kQKV = gemm2<false, true, true, true, false, false, false, true, false>;
    auto kScores = gemm2<true, true, false, false, false, true, false, false, false>;
    auto kCtx = gemm2<false, true, false, false, true, false, true, false, false>;
    auto kOut = gemm2<false, false, true, false, false, false, false, false, true>;

    cudaFuncSetAttribute(kQKV, cudaFuncAttributeMaxDynamicSharedMemorySize, SMEM_BYTES);
    cudaFuncSetAttribute(kScores, cudaFuncAttributeMaxDynamicSharedMemorySize, SMEM_BYTES);
    cudaFuncSetAttribute(kCtx, cudaFuncAttributeMaxDynamicSharedMemorySize, SMEM_BYTES_N);
    cudaFuncSetAttribute(kOut, cudaFuncAttributeMaxDynamicSharedMemorySize, SMEM_BYTES);

    const float scale = 0.03608439182435161f;  // 1/sqrt(768)

    // fp32 -> fp16 weight conversions (x is consumed fp32 directly by QKV GEMM)
    {
        const long nValid4 = ((long)VOC * EMB) / 4;
        const long nTot4 = ((long)KPAD * EMB) / 4;
        cvt_tail4<<<8192, 256>>>((const float4*)Wq, (uint2*)pWqh, nValid4, nTot4);
        cvt_tail4<<<8192, 256>>>((const float4*)Wk, (uint2*)pWkh, nValid4, nTot4);
        cvt_tail4<<<8192, 256>>>((const float4*)Wv, (uint2*)pWvh, nValid4, nTot4);
    }
    cvt_pad2d<<<dim3((NPAD / 2 + 255) / 256, EMB), 256>>>(Wo, (__half2*)pWoh, VOC, NPAD / 2);

    // fused QKV projections: A = raw fp32 x (in-kernel convert), K loop = KPAD.
    // lda = VOC (fp32 row stride == valid width). Q gets 1/sqrt(d) folded in.
    kQKV<<<dim3(18, 16), THREADS, SMEM_BYTES>>>(
        nullptr, x, pWqh, pWkh, pWvh, bq, bk, bv,
        nullptr, pQ, pK, pV, nullptr,
        SEQ, EMB, KPAD, VOC, EMB, EMB, scale);

    // expS = exp(Qs @ K^T)  (fp16, unnormalized)
    kScores<<<dim3(16, 16), THREADS, SMEM_BYTES>>>(
        pQ, nullptr, pK, nullptr, nullptr, nullptr, nullptr, nullptr,
        nullptr, pAttn, nullptr, nullptr, nullptr,
        SEQ, SEQ, EMB, EMB, EMB, SEQ, 1.0f);

    // rowsum[r] = sum_k expS[r][k]
    rowsum_kernel<<<SEQ, 256>>>((const __half2*)pAttn, pRS);

    // ctx = (expS @ V) / rowsum   (narrow BN=64)
    kCtx<<<dim3(12, 16), THREADS, SMEM_BYTES_N>>>(
        pAttn, nullptr, pV, nullptr, nullptr, nullptr, nullptr, nullptr,
        nullptr, pCtx, nullptr, nullptr, pRS,
        SEQ, EMB, SEQ, SEQ, EMB, EMB, 1.0f);

    // out = ctx @ Wo + bo   (GRIDT: row-block fastest -> Wo L2 reuse per wave)
    kOut<<<dim3(16, NPAD / BN), THREADS, SMEM_BYTES>>>(
        pCtx, nullptr, pWoh, nullptr, nullptr, bo, nullptr, nullptr,
        out, nullptr, nullptr, nullptr, nullptr,
        SEQ, VOC, EMB, EMB, NPAD, VOC, 1.0f);
}

// round 14
// speedup vs baseline: 2.3785x; 2.3785x over previous
#include <cuda_runtime.h>
#include <cuda_fp16.h>
#include <stdint.h>

static constexpr int SEQ  = 2048;
static constexpr int VOC  = 50257;
static constexpr int EMB  = 768;
static constexpr int KPAD = 50304;   // VOC padded to multiple of 64 (K of QKV gemm)
static constexpr int NPAD = 50304;   // VOC padded to multiple of 128 (N of out gemm)

#define BM 128
#define BN 128
#define BK 64
#define STAGES 3
#define THREADS 256
#define A_STRIDE 72                       // 64+8 halfs -> 144B rows, ldsm conflict-free
#define BNT_STRIDE 136                    // non-BT wide B rows: 128+8 halfs
#define BNT_STRIDE_N 72                   // non-BT narrow B rows: 64+8 halfs
#define A_HALF_PER_STAGE (BM * A_STRIDE)  // 9216
#define B_HALF_WIDE (BM * A_STRIDE)       // 9216 (>= 64*136 = 8704)
#define B_HALF_NARROW (64 * BNT_STRIDE_N) // 4608
#define SMEM_BYTES  (STAGES * (A_HALF_PER_STAGE + B_HALF_WIDE) * 2)     // 110592
#define SMEM_BYTES_N (STAGES * (A_HALF_PER_STAGE + B_HALF_NARROW) * 2)  // 82944

// ---------------- scratch (__device__ globals; no allocation allowed) ---------
__device__ __half g_xh[(size_t)SEQ * KPAD];
__device__ __half g_Wqh[(size_t)KPAD * EMB];
__device__ __half g_Wkh[(size_t)KPAD * EMB];
__device__ __half g_Wvh[(size_t)KPAD * EMB];
__device__ __half g_Woh[(size_t)EMB * NPAD];
__device__ __half g_Q[SEQ * EMB];
__device__ __half g_Km[SEQ * EMB];
__device__ __half g_V[SEQ * EMB];
__device__ __half g_attn[(size_t)SEQ * SEQ];   // exp(scores), unnormalized
__device__ float  g_rowsum[SEQ];
__device__ __half g_ctx[SEQ * EMB];

// ---------------- helpers ----------------------------------------------------
__device__ __forceinline__ void cp_async16(uint32_t dst, const void* src) {
    asm volatile("cp.async.cg.shared.global [%0], [%1], 16;\n" :: "r"(dst), "l"(src));
}
__device__ __forceinline__ void cp_commit() {
    asm volatile("cp.async.commit_group;\n");
}
__device__ __forceinline__ void cp_wait() {
    asm volatile("cp.async.wait_group %0;\n" :: "n"(STAGES - 2));
}
__device__ __forceinline__ void ldsm_x4(uint32_t* r, uint32_t addr) {
    asm volatile("ldmatrix.sync.aligned.m8n8.x4.shared.b16 {%0,%1,%2,%3}, [%4];\n"
                 : "=r"(r[0]), "=r"(r[1]), "=r"(r[2]), "=r"(r[3]) : "r"(addr));
}
__device__ __forceinline__ void ldsm_x4_t(uint32_t* r, uint32_t addr) {
    asm volatile("ldmatrix.sync.aligned.m8n8.x4.trans.shared.b16 {%0,%1,%2,%3}, [%4];\n"
                 : "=r"(r[0]), "=r"(r[1]), "=r"(r[2]), "=r"(r[3]) : "r"(addr));
}
__device__ __forceinline__ void mma16816(float* c, const uint32_t* a, const uint32_t* b) {
    asm volatile(
        "mma.sync.aligned.m16n8k16.row.col.f32.f16.f16.f32 "
        "{%0,%1,%2,%3}, {%4,%5,%6,%7}, {%8,%9}, {%0,%1,%2,%3};\n"
        : "+f"(c[0]), "+f"(c[1]), "+f"(c[2]), "+f"(c[3])
        : "r"(a[0]), "r"(a[1]), "r"(a[2]), "r"(a[3]), "r"(b[0]), "r"(b[1]));
}
// Fast exp on the FMA pipe (no MUFU); valid for |score| within clamp range.
__device__ __forceinline__ float fast_exp(float x) {
    float y = x * 1.4426950408889634f;
    y = fminf(fmaxf(y, -100.0f), 15.5f);
    const float t = y + 12582912.0f;      // 1.5 * 2^23
    const float nf = t - 12582912.0f;
    const float f = y - nf;
    const int n = (int)nf;
    float p = 0.00133335581f;
    p = fmaf(p, f, 0.00961812910f);
    p = fmaf(p, f, 0.0555041086f);
    p = fmaf(p, f, 0.240226507f);
    p = fmaf(p, f, 0.693147182f);
    p = fmaf(p, f, 1.0f);
    return p * __int_as_float((n + 127) << 23);
}

// ---------------- conversion kernels -----------------------------------------
__global__ __launch_bounds__(256) void cvt_pad2d(const float* __restrict__ s,
                                                 __half2* __restrict__ d,
                                                 int srcW, int dstW2) {
    const int c2 = blockIdx.x * 256 + threadIdx.x;
    const size_t row = blockIdx.y;
    if (c2 < dstW2) {
        const int col = c2 * 2;
        const float* sr = s + row * (size_t)srcW;
        const float v0 = (col < srcW) ? sr[col] : 0.f;
        const float v1 = (col + 1 < srcW) ? sr[col + 1] : 0.f;
        d[row * (size_t)dstW2 + c2] = __floats2half2_rn(v0, v1);
    }
}
__global__ __launch_bounds__(256) void cvt_tail4(const float4* __restrict__ s,
                                                 uint2* __restrict__ d,
                                                 long nValid4, long nTotal4) {
    long i = (long)blockIdx.x * blockDim.x + threadIdx.x;
    const long stride = (long)gridDim.x * blockDim.x;
    for (; i < nTotal4; i += stride) {
        float4 v = (i < nValid4) ? s[i] : make_float4(0.f, 0.f, 0.f, 0.f);
        __half2 lo = __floats2half2_rn(v.x, v.y);
        __half2 hi = __floats2half2_rn(v.z, v.w);
        uint2 o;
        o.x = *(const uint32_t*)&lo;
        o.y = *(const uint32_t*)&hi;
        d[i] = o;
    }
}

// ---------------- pipelined fp16 GEMM (BK=64, 3 stages, 2 CTA/SM) -------------
// C[M,N] = A[M,K] @ B (+bias)*alpha.  B row-major [K,N] if !BT, [N,K] if BT.
// NARROW: BN=64.  EXPOUT: write fp16 exp(acc), no guards.
// NORM: multiply by 1/rowsum[row] in epilogue.  GRIDT: row-block on blockIdx.x.
template <bool BT, bool OUT_HALF, bool HAS_BIAS, bool FUSED3, bool NARROW,
          bool EXPOUT, bool NORM, bool GRIDT>
__global__ __launch_bounds__(THREADS, 2) void gemm2(
    const __half* __restrict__ A,
    const __half* __restrict__ B0, const __half* __restrict__ B1, const __half* __restrict__ B2,
    const float* __restrict__ bias0, const float* __restrict__ bias1, const float* __restrict__ bias2,
    float* __restrict__ Cf,
    __half* __restrict__ Ch0, __half* __restrict__ Ch1, __half* __restrict__ Ch2,
    const float* __restrict__ rowsum,
    int M, int N, int K, int lda, int ldb, int ldc, float alpha)
{
    constexpr int BN_E = NARROW ? 64 : 128;
    constexpr int MI = NARROW ? 2 : 4;
    constexpr int B_HALF_STG = NARROW ? B_HALF_NARROW : B_HALF_WIDE;
    constexpr int BS_NT = NARROW ? BNT_STRIDE_N : BNT_STRIDE;

    extern __shared__ __half sm[];
    __half* As = sm;
    __half* Bs = sm + STAGES * A_HALF_PER_STAGE;

    const int tid = threadIdx.x;
    const int row0 = (GRIDT ? blockIdx.x : blockIdx.y) * BM;

    const __half* B = B0;
    const float* bias = bias0;
    __half* Ch = Ch0;
    float aScale = alpha;
    int col0;
    if constexpr (FUSED3) {
        const int blocksPer = N / BN_E;
        const int sel = blockIdx.x / blocksPer;
        col0 = (blockIdx.x % blocksPer) * BN_E;
        if (sel == 1) { B = B1; bias = bias1; Ch = Ch1; aScale = 1.f; }
        else if (sel == 2) { B = B2; bias = bias2; Ch = Ch2; aScale = 1.f; }
    } else {
        col0 = (GRIDT ? blockIdx.y : blockIdx.x) * BN_E;
    }

    const uint32_t smA = (uint32_t)__cvta_generic_to_shared(As);
    const uint32_t smB = (uint32_t)__cvta_generic_to_shared(Bs);

    const int nTiles = K / BK;

    auto loadStage = [&](int t, int slot) {
        const int k0 = t * BK;
#pragma unroll
        for (int h = 0; h < 4; h++) {
            const int c = tid + h * 256;
            const int row = c >> 3, kc = (c & 7) * 8;
            const uint32_t dst = smA + (uint32_t)(slot * A_HALF_PER_STAGE + row * A_STRIDE + kc) * 2;
            cp_async16(dst, A + (size_t)(row0 + row) * lda + (k0 + kc));
        }
        if constexpr (BT) {
#pragma unroll
            for (int h = 0; h < 4; h++) {
                const int c = tid + h * 256;
                const int nr = c >> 3, kc = (c & 7) * 8;
                const uint32_t dst = smB + (uint32_t)(slot * B_HALF_STG + nr * A_STRIDE + kc) * 2;
                cp_async16(dst, B + (size_t)(col0 + nr) * ldb + (k0 + kc));
            }
        } else if constexpr (NARROW) {
#pragma unroll
            for (int h = 0; h < 2; h++) {
                const int c = tid + h * 256;
                const int kr = c >> 3, nc = (c & 7) * 8;
                const uint32_t dst = smB + (uint32_t)(slot * B_HALF_STG + kr * BS_NT + nc) * 2;
                cp_async16(dst, B + (size_t)(k0 + kr) * ldb + (col0 + nc));
            }
        } else {
#pragma unroll
            for (int h = 0; h < 4; h++) {
                const int c = tid + h * 256;
                const int kr = c >> 4, nc = (c & 15) * 8;
                const uint32_t dst = smB + (uint32_t)(slot * B_HALF_STG + kr * BS_NT + nc) * 2;
                cp_async16(dst, B + (size_t)(k0 + kr) * ldb + (col0 + nc));
            }
        }
    };

    const int warp = tid >> 5, lane = tid & 31;
    const int wm = NARROW ? (warp & 3) * 32 : (warp & 1) * 64;
    const int wn = NARROW ? (warp >> 2) * 32 : (warp >> 1) * 32;
    const int g = lane >> 2, t4 = lane & 3;
    const int lrow = lane & 15;
    const int lcol8 = (lane >> 4) << 3;
    const int mrow = lane & 7;
    const int msel = lane >> 3;

    float acc[MI][4][4];
#pragma unroll
    for (int mi = 0; mi < MI; mi++)
#pragma unroll
        for (int ni = 0; ni < 4; ni++)
#pragma unroll
            for (int q = 0; q < 4; q++) acc[mi][ni][q] = 0.f;

#pragma unroll
    for (int s = 0; s < STAGES - 1; s++) {
        loadStage(s, s);
        cp_commit();
    }

    for (int t = 0; t < nTiles; t++) {
        cp_wait();
        __syncthreads();

        const int slot = t % STAGES;
        const uint32_t aBase = smA + (uint32_t)(slot * A_HALF_PER_STAGE) * 2;
        const uint32_t bBase = smB + (uint32_t)(slot * B_HALF_STG) * 2;

        auto computeK = [&](int ks) {
            uint32_t a[MI][4];
#pragma unroll
            for (int mi = 0; mi < MI; mi++) {
                const uint32_t addr = aBase + (uint32_t)((wm + mi * 16 + lrow) * A_STRIDE + ks + lcol8) * 2;
                ldsm_x4(a[mi], addr);
            }
            uint32_t b[4][2];
            if constexpr (BT) {
#pragma unroll
                for (int nj = 0; nj < 2; nj++) {
                    uint32_t r[4];
                    const int n = wn + nj * 16 + ((msel >> 1) << 3) + mrow;
                    const int kk = ks + ((msel & 1) << 3);
                    ldsm_x4(r, bBase + (uint32_t)(n * A_STRIDE + kk) * 2);
                    b[nj * 2][0] = r[0]; b[nj * 2][1] = r[1];
                    b[nj * 2 + 1][0] = r[2]; b[nj * 2 + 1][1] = r[3];
                }
            } else {
#pragma unroll
                for (int nj = 0; nj < 2; nj++) {
                    uint32_t r[4];
                    const uint32_t addr = bBase + (uint32_t)((ks + lrow) * BS_NT + wn + nj * 16 + lcol8) * 2;
                    ldsm_x4_t(r, addr);
                    b[nj * 2][0] = r[0]; b[nj * 2][1] = r[1];
                    b[nj * 2 + 1][0] = r[2]; b[nj * 2 + 1][1] = r[3];
                }
            }
#pragma unroll
            for (int mi = 0; mi < MI; mi++)
#pragma unroll
                for (int ni = 0; ni < 4; ni++)
                    mma16816(acc[mi][ni], a[mi], b[ni]);
        };

        computeK(0);

        const int nt = t + STAGES - 1;
        if (nt < nTiles) loadStage(nt, nt % STAGES);
        cp_commit();

        computeK(16);
        computeK(32);
        computeK(48);
    }

    // ---------------- epilogue ----------------
    float invr[MI][2];
    if constexpr (NORM) {
#pragma unroll
        for (int mi = 0; mi < MI; mi++)
#pragma unroll
            for (int hr = 0; hr < 2; hr++)
                invr[mi][hr] = 1.0f / rowsum[row0 + wm + mi * 16 + g + hr * 8];
    }

#pragma unroll
    for (int mi = 0; mi < MI; mi++) {
#pragma unroll
        for (int ni = 0; ni < 4; ni++) {
            const int r = row0 + wm + mi * 16 + g;
            const int cn = col0 + wn + ni * 8 + t4 * 2;
            if constexpr (EXPOUT) {
#pragma unroll
                for (int hr = 0; hr < 2; hr++) {
                    const int rr = r + hr * 8;
                    const float e0 = fast_exp(acc[mi][ni][hr * 2]);
                    const float e1 = fast_exp(acc[mi][ni][hr * 2 + 1]);
                    *(__half2*)(Ch + (size_t)rr * ldc + cn) = __floats2half2_rn(e0, e1);
                }
            } else if constexpr (OUT_HALF) {
#pragma unroll
                for (int hr = 0; hr < 2; hr++) {
                    const int rr = r + hr * 8;
                    float v0 = acc[mi][ni][hr * 2];
                    float v1 = acc[mi][ni][hr * 2 + 1];
                    if constexpr (HAS_BIAS) { v0 += bias[cn]; v1 += bias[cn + 1]; }
                    if constexpr (NORM) { v0 *= invr[mi][hr]; v1 *= invr[mi][hr]; }
                    else                { v0 *= aScale;       v1 *= aScale; }
                    *(__half2*)(Ch + (size_t)rr * ldc + cn) = __floats2half2_rn(v0, v1);
                }
            } else {
#pragma unroll
                for (int q = 0; q < 4; q++) {
                    const int rr = r + (q >> 1) * 8;
                    const int cc = cn + (q & 1);
                    if (cc < N) {
                        float bv = 0.f;
                        if constexpr (HAS_BIAS) bv = bias[cc];
                        Cf[(size_t)rr * ldc + cc] = (acc[mi][ni][q] + bv) * aScale;
                    }
                }
            }
        }
    }
}

// ---------------- row-sum of exp-scores (deterministic) -----------------------
__global__ __launch_bounds__(256) void rowsum_kernel(
    const __half2* __restrict__ E_, float* __restrict__ rs)
{
    __shared__ float red[8];
    const int row = blockIdx.x;
    const __half2* e = E_ + (size_t)row * (SEQ / 2);
    const int tid = threadIdx.x;

    float s = 0.f;
#pragma unroll
    for (int j = 0; j < 4; j++) {
        const float2 v = __half22float2(e[tid + j * 256]);
        s += v.x + v.y;
    }
#pragma unroll
    for (int o = 16; o; o >>= 1) s += __shfl_xor_sync(0xffffffffu, s, o);
    if ((tid & 31) == 0) red[tid >> 5] = s;
    __syncthreads();
    if (tid == 0) {
        float tot = 0.f;
#pragma unroll
        for (int i = 0; i < 8; i++) tot += red[i];
        rs[row] = tot;
    }
}

// ---------------- launch ------------------------------------------------------
extern "C" void kernel_launch(void* const* d_in, const int* in_sizes, int n_in,
                              void* d_out, int out_size)
{
    const float* x  = (const float*)d_in[0];
    const float* Wq = (const float*)d_in[1];
    const float* bq = (const float*)d_in[2];
    const float* Wk = (const float*)d_in[3];
    const float* bk = (const float*)d_in[4];
    const float* Wv = (const float*)d_in[5];
    const float* bv = (const float*)d_in[6];
    const float* Wo = (const float*)d_in[7];
    const float* bo = (const float*)d_in[8];
    float* out = (float*)d_out;

    __half *pxh, *pWqh, *pWkh, *pWvh, *pWoh, *pQ, *pK, *pV, *pAttn, *pCtx;
    float* pRS;
    cudaGetSymbolAddress((void**)&pxh, g_xh);
    cudaGetSymbolAddress((void**)&pWqh, g_Wqh);
    cudaGetSymbolAddress((void**)&pWkh, g_Wkh);
    cudaGetSymbolAddress((void**)&pWvh, g_Wvh);
    cudaGetSymbolAddress((void**)&pWoh, g_Woh);
    cudaGetSymbolAddress((void**)&pQ, g_Q);
    cudaGetSymbolAddress((void**)&pK, g_Km);
    cudaGetSymbolAddress((void**)&pV, g_V);
    cudaGetSymbolAddress((void**)&pAttn, g_attn);
    cudaGetSymbolAddress((void**)&pRS, g_rowsum);
    cudaGetSymbolAddress((void**)&pCtx, g_ctx);

    auto kQKV = gemm2<false, true, true, true, false, false, false, false>;
    auto kScores = gemm2<true, true, false, false, false, true, false, false>;
    auto kCtx = gemm2<false, true, false, false, true, false, true, false>;
    auto kOut = gemm2<false, false, true, false, false, false, false, true>;

    cudaFuncSetAttribute(kQKV, cudaFuncAttributeMaxDynamicSharedMemorySize, SMEM_BYTES);
    cudaFuncSetAttribute(kScores, cudaFuncAttributeMaxDynamicSharedMemorySize, SMEM_BYTES);
    cudaFuncSetAttribute(kCtx, cudaFuncAttributeMaxDynamicSharedMemorySize, SMEM_BYTES_N);
    cudaFuncSetAttribute(kOut, cudaFuncAttributeMaxDynamicSharedMemorySize, SMEM_BYTES);

    const float scale = 0.03608439182435161f;  // 1/sqrt(768)

    // fp32 -> fp16 with padding
    cvt_pad2d<<<dim3((KPAD / 2 + 255) / 256, SEQ), 256>>>(x, (__half2*)pxh, VOC, KPAD / 2);
    {
        const long nValid4 = ((long)VOC * EMB) / 4;
        const long nTot4 = ((long)KPAD * EMB) / 4;
        cvt_tail4<<<8192, 256>>>((const float4*)Wq, (uint2*)pWqh, nValid4, nTot4);
        cvt_tail4<<<8192, 256>>>((const float4*)Wk, (uint2*)pWkh, nValid4, nTot4);
        cvt_tail4<<<8192, 256>>>((const float4*)Wv, (uint2*)pWvh, nValid4, nTot4);
    }
    cvt_pad2d<<<dim3((NPAD / 2 + 255) / 256, EMB), 256>>>(Wo, (__half2*)pWoh, VOC, NPAD / 2);

    // fused QKV projections (K = KPAD; pad rows zero). Q gets 1/sqrt(d) folded in.
    kQKV<<<dim3(18, 16), THREADS, SMEM_BYTES>>>(
        pxh, pWqh, pWkh, pWvh, bq, bk, bv,
        nullptr, pQ, pK, pV, nullptr,
        SEQ, EMB, KPAD, KPAD, EMB, EMB, scale);

    // expS = exp(Qs @ K^T)  (fp16, unnormalized)
    kScores<<<dim3(16, 16), THREADS, SMEM_BYTES>>>(
        pQ, pK, nullptr, nullptr, nullptr, nullptr, nullptr,
        nullptr, pAttn, nullptr, nullptr, nullptr,
        SEQ, SEQ, EMB, EMB, EMB, SEQ, 1.0f);

    // rowsum[r] = sum_k expS[r][k]
    rowsum_kernel<<<SEQ, 256>>>((const __half2*)pAttn, pRS);

    // ctx = (expS @ V) / rowsum   (narrow BN=64: 192 CTAs)
    kCtx<<<dim3(12, 16), THREADS, SMEM_BYTES_N>>>(
        pAttn, pV, nullptr, nullptr, nullptr, nullptr, nullptr,
        nullptr, pCtx, nullptr, nullptr, pRS,
        SEQ, EMB, SEQ, SEQ, EMB, EMB, 1.0f);

    // out = ctx @ Wo + bo   (GRIDT: row-block fastest -> Wo reused 16x per wave via L2)
    kOut<<<dim3(16, NPAD / BN), THREADS, SMEM_BYTES>>>(
        pCtx, pWoh, nullptr, nullptr, bo, nullptr, nullptr,
        out, nullptr, nullptr, nullptr, nullptr,
        SEQ, VOC, EMB, EMB, NPAD, VOC, 1.0f);
}

// round 15
// speedup vs baseline: 2.4378x; 1.0249x over previous
#include <cuda_runtime.h>
#include <cuda_fp16.h>
#include <stdint.h>

static constexpr int SEQ  = 2048;
static constexpr int VOC  = 50257;
static constexpr int EMB  = 768;
static constexpr int KPAD = 50304;   // VOC padded to multiple of 64 (K of QKV gemm)
static constexpr int NPAD = 50304;   // VOC padded to multiple of 128 (N of out gemm)

#define BM 128
#define BN 128
#define BK 64
#define STAGES 3
#define THREADS 256
#define A_STRIDE 72                       // 64+8 halfs -> 144B rows, ldsm conflict-free
#define BNT_STRIDE 136                    // non-BT wide B rows: 128+8 halfs
#define BNT_STRIDE_N 72                   // non-BT narrow B rows: 64+8 halfs
#define A_HALF_PER_STAGE (BM * A_STRIDE)  // 9216
#define B_HALF_WIDE (BM * A_STRIDE)       // 9216 (>= 64*136 = 8704)
#define B_HALF_NARROW (64 * BNT_STRIDE_N) // 4608
#define SMEM_BYTES  (STAGES * (A_HALF_PER_STAGE + B_HALF_WIDE) * 2)     // 110592
#define SMEM_BYTES_N (STAGES * (A_HALF_PER_STAGE + B_HALF_NARROW) * 2)  // 82944

// ---------------- scratch (__device__ globals; no allocation allowed) ---------
__device__ __half g_xh[(size_t)SEQ * KPAD];
__device__ __half g_Wqh[(size_t)KPAD * EMB];
__device__ __half g_Wkh[(size_t)KPAD * EMB];
__device__ __half g_Wvh[(size_t)KPAD * EMB];
__device__ __half g_Woh[(size_t)EMB * NPAD];
__device__ __half g_Q[SEQ * EMB];
__device__ __half g_Km[SEQ * EMB];
__device__ __half g_V[SEQ * EMB];
__device__ __half g_attn[(size_t)SEQ * SEQ];   // exp(scores), unnormalized
__device__ float  g_rowsum[SEQ];
__device__ __half g_ctx[SEQ * EMB];

// ---------------- helpers ----------------------------------------------------
__device__ __forceinline__ void cp_async16(uint32_t dst, const void* src) {
    asm volatile("cp.async.cg.shared.global [%0], [%1], 16;\n" :: "r"(dst), "l"(src));
}
__device__ __forceinline__ void cp_commit() {
    asm volatile("cp.async.commit_group;\n");
}
__device__ __forceinline__ void cp_wait() {
    asm volatile("cp.async.wait_group %0;\n" :: "n"(STAGES - 2));
}
__device__ __forceinline__ void ldsm_x4(uint32_t* r, uint32_t addr) {
    asm volatile("ldmatrix.sync.aligned.m8n8.x4.shared.b16 {%0,%1,%2,%3}, [%4];\n"
                 : "=r"(r[0]), "=r"(r[1]), "=r"(r[2]), "=r"(r[3]) : "r"(addr));
}
__device__ __forceinline__ void ldsm_x4_t(uint32_t* r, uint32_t addr) {
    asm volatile("ldmatrix.sync.aligned.m8n8.x4.trans.shared.b16 {%0,%1,%2,%3}, [%4];\n"
                 : "=r"(r[0]), "=r"(r[1]), "=r"(r[2]), "=r"(r[3]) : "r"(addr));
}
__device__ __forceinline__ void mma16816(float* c, const uint32_t* a, const uint32_t* b) {
    asm volatile(
        "mma.sync.aligned.m16n8k16.row.col.f32.f16.f16.f32 "
        "{%0,%1,%2,%3}, {%4,%5,%6,%7}, {%8,%9}, {%0,%1,%2,%3};\n"
        : "+f"(c[0]), "+f"(c[1]), "+f"(c[2]), "+f"(c[3])
        : "r"(a[0]), "r"(a[1]), "r"(a[2]), "r"(a[3]), "r"(b[0]), "r"(b[1]));
}
// Fast exp on the FMA pipe (no MUFU); valid for |score| within clamp range.
__device__ __forceinline__ float fast_exp(float x) {
    float y = x * 1.4426950408889634f;
    y = fminf(fmaxf(y, -100.0f), 15.5f);
    const float t = y + 12582912.0f;      // 1.5 * 2^23
    const float nf = t - 12582912.0f;
    const float f = y - nf;
    const int n = (int)nf;
    float p = 0.00133335581f;
    p = fmaf(p, f, 0.00961812910f);
    p = fmaf(p, f, 0.0555041086f);
    p = fmaf(p, f, 0.240226507f);
    p = fmaf(p, f, 0.693147182f);
    p = fmaf(p, f, 1.0f);
    return p * __int_as_float((n + 127) << 23);
}

// ---------------- conversion kernels (MLP-boosted) ----------------------------
// Row-padded convert: 4 half2 outputs per thread (8 scalar LDGs in flight),
// uint4 fast-path store (dstW2 divisible by 4 -> 16B-aligned groups).
__global__ __launch_bounds__(256) void cvt_pad2d(const float* __restrict__ s,
                                                 __half2* __restrict__ d,
                                                 int srcW, int dstW2) {
    const int c2base = (blockIdx.x * 256 + threadIdx.x) * 4;
    const size_t row = blockIdx.y;
    if (c2base >= dstW2) return;
    const float* sr = s + row * (size_t)srcW;
    __half2* dr = d + row * (size_t)dstW2;

    const int colLast = (c2base + 3) * 2 + 1;
    if (colLast < srcW) {
        // fast path: all 8 source cols valid
        float v[8];
#pragma unroll
        for (int j = 0; j < 8; j++) v[j] = sr[c2base * 2 + j];
        uint4 o;
        __half2 h0 = __floats2half2_rn(v[0], v[1]);
        __half2 h1 = __floats2half2_rn(v[2], v[3]);
        __half2 h2 = __floats2half2_rn(v[4], v[5]);
        __half2 h3 = __floats2half2_rn(v[6], v[7]);
        o.x = *(uint32_t*)&h0; o.y = *(uint32_t*)&h1;
        o.z = *(uint32_t*)&h2; o.w = *(uint32_t*)&h3;
        *(uint4*)(dr + c2base) = o;
    } else {
        // tail path: per-element guards
#pragma unroll
        for (int u = 0; u < 4; u++) {
            const int c2 = c2base + u;
            if (c2 < dstW2) {
                const int col = c2 * 2;
                const float v0 = (col < srcW) ? sr[col] : 0.f;
                const float v1 = (col + 1 < srcW) ? sr[col + 1] : 0.f;
                dr[c2] = __floats2half2_rn(v0, v1);
            }
        }
    }
}
// Contiguous convert, 4-way unrolled grid-stride (4 float4 LDGs in flight).
__global__ __launch_bounds__(256) void cvt_tail4(const float4* __restrict__ s,
                                                 uint2* __restrict__ d,
                                                 long nValid4, long nTotal4) {
    const long tid0 = (long)blockIdx.x * blockDim.x + threadIdx.x;
    const long stride = (long)gridDim.x * blockDim.x;
    for (long base = tid0; base < nTotal4; base += 4 * stride) {
        float4 v[4];
#pragma unroll
        for (int u = 0; u < 4; u++) {
            const long idx = base + u * stride;
            v[u] = (idx < nTotal4 && idx < nValid4) ? s[idx]
                                                    : make_float4(0.f, 0.f, 0.f, 0.f);
        }
#pragma unroll
        for (int u = 0; u < 4; u++) {
            const long idx = base + u * stride;
            if (idx < nTotal4) {
                __half2 lo = __floats2half2_rn(v[u].x, v[u].y);
                __half2 hi = __floats2half2_rn(v[u].z, v[u].w);
                uint2 o;
                o.x = *(const uint32_t*)&lo;
                o.y = *(const uint32_t*)&hi;
                d[idx] = o;
            }
        }
    }
}

// ---------------- pipelined fp16 GEMM (BK=64, 3 stages, 2 CTA/SM) -------------
// C[M,N] = A[M,K] @ B (+bias)*alpha.  B row-major [K,N] if !BT, [N,K] if BT.
// NARROW: BN=64.  EXPOUT: write fp16 exp(acc), no guards.
// NORM: multiply by 1/rowsum[row] in epilogue.  GRIDT: row-block on blockIdx.x.
template <bool BT, bool OUT_HALF, bool HAS_BIAS, bool FUSED3, bool NARROW,
          bool EXPOUT, bool NORM, bool GRIDT>
__global__ __launch_bounds__(THREADS, 2) void gemm2(
    const __half* __restrict__ A,
    const __half* __restrict__ B0, const __half* __restrict__ B1, const __half* __restrict__ B2,
    const float* __restrict__ bias0, const float* __restrict__ bias1, const float* __restrict__ bias2,
    float* __restrict__ Cf,
    __half* __restrict__ Ch0, __half* __restrict__ Ch1, __half* __restrict__ Ch2,
    const float* __restrict__ rowsum,
    int M, int N, int K, int lda, int ldb, int ldc, float alpha)
{
    constexpr int BN_E = NARROW ? 64 : 128;
    constexpr int MI = NARROW ? 2 : 4;
    constexpr int B_HALF_STG = NARROW ? B_HALF_NARROW : B_HALF_WIDE;
    constexpr int BS_NT = NARROW ? BNT_STRIDE_N : BNT_STRIDE;

    extern __shared__ __half sm[];
    __half* As = sm;
    __half* Bs = sm + STAGES * A_HALF_PER_STAGE;

    const int tid = threadIdx.x;
    const int row0 = (GRIDT ? blockIdx.x : blockIdx.y) * BM;

    const __half* B = B0;
    const float* bias = bias0;
    __half* Ch = Ch0;
    float aScale = alpha;
    int col0;
    if constexpr (FUSED3) {
        const int blocksPer = N / BN_E;
        const int sel = blockIdx.x / blocksPer;
        col0 = (blockIdx.x % blocksPer) * BN_E;
        if (sel == 1) { B = B1; bias = bias1; Ch = Ch1; aScale = 1.f; }
        else if (sel == 2) { B = B2; bias = bias2; Ch = Ch2; aScale = 1.f; }
    } else {
        col0 = (GRIDT ? blockIdx.y : blockIdx.x) * BN_E;
    }

    const uint32_t smA = (uint32_t)__cvta_generic_to_shared(As);
    const uint32_t smB = (uint32_t)__cvta_generic_to_shared(Bs);

    const int nTiles = K / BK;

    auto loadStage = [&](int t, int slot) {
        const int k0 = t * BK;
#pragma unroll
        for (int h = 0; h < 4; h++) {
            const int c = tid + h * 256;
            const int row = c >> 3, kc = (c & 7) * 8;
            const uint32_t dst = smA + (uint32_t)(slot * A_HALF_PER_STAGE + row * A_STRIDE + kc) * 2;
            cp_async16(dst, A + (size_t)(row0 + row) * lda + (k0 + kc));
        }
        if constexpr (BT) {
#pragma unroll
            for (int h = 0; h < 4; h++) {
                const int c = tid + h * 256;
                const int nr = c >> 3, kc = (c & 7) * 8;
                const uint32_t dst = smB + (uint32_t)(slot * B_HALF_STG + nr * A_STRIDE + kc) * 2;
                cp_async16(dst, B + (size_t)(col0 + nr) * ldb + (k0 + kc));
            }
        } else if constexpr (NARROW) {
#pragma unroll
            for (int h = 0; h < 2; h++) {
                const int c = tid + h * 256;
                const int kr = c >> 3, nc = (c & 7) * 8;
                const uint32_t dst = smB + (uint32_t)(slot * B_HALF_STG + kr * BS_NT + nc) * 2;
                cp_async16(dst, B + (size_t)(k0 + kr) * ldb + (col0 + nc));
            }
        } else {
#pragma unroll
            for (int h = 0; h < 4; h++) {
                const int c = tid + h * 256;
                const int kr = c >> 4, nc = (c & 15) * 8;
                const uint32_t dst = smB + (uint32_t)(slot * B_HALF_STG + kr * BS_NT + nc) * 2;
                cp_async16(dst, B + (size_t)(k0 + kr) * ldb + (col0 + nc));
            }
        }
    };

    const int warp = tid >> 5, lane = tid & 31;
    const int wm = NARROW ? (warp & 3) * 32 : (warp & 1) * 64;
    const int wn = NARROW ? (warp >> 2) * 32 : (warp >> 1) * 32;
    const int g = lane >> 2, t4 = lane & 3;
    const int lrow = lane & 15;
    const int lcol8 = (lane >> 4) << 3;
    const int mrow = lane & 7;
    const int msel = lane >> 3;

    float acc[MI][4][4];
#pragma unroll
    for (int mi = 0; mi < MI; mi++)
#pragma unroll
        for (int ni = 0; ni < 4; ni++)
#pragma unroll
            for (int q = 0; q < 4; q++) acc[mi][ni][q] = 0.f;

#pragma unroll
    for (int s = 0; s < STAGES - 1; s++) {
        loadStage(s, s);
        cp_commit();
    }

    for (int t = 0; t < nTiles; t++) {
        cp_wait();
        __syncthreads();

        const int slot = t % STAGES;
        const uint32_t aBase = smA + (uint32_t)(slot * A_HALF_PER_STAGE) * 2;
        const uint32_t bBase = smB + (uint32_t)(slot * B_HALF_STG) * 2;

        auto computeK = [&](int ks) {
            uint32_t a[MI][4];
#pragma unroll
            for (int mi = 0; mi < MI; mi++) {
                const uint32_t addr = aBase + (uint32_t)((wm + mi * 16 + lrow) * A_STRIDE + ks + lcol8) * 2;
                ldsm_x4(a[mi], addr);
            }
            uint32_t b[4][2];
            if constexpr (BT) {
#pragma unroll
                for (int nj = 0; nj < 2; nj++) {
                    uint32_t r[4];
                    const int n = wn + nj * 16 + ((msel >> 1) << 3) + mrow;
                    const int kk = ks + ((msel & 1) << 3);
                    ldsm_x4(r, bBase + (uint32_t)(n * A_STRIDE + kk) * 2);
                    b[nj * 2][0] = r[0]; b[nj * 2][1] = r[1];
                    b[nj * 2 + 1][0] = r[2]; b[nj * 2 + 1][1] = r[3];
                }
            } else {
#pragma unroll
                for (int nj = 0; nj < 2; nj++) {
                    uint32_t r[4];
                    const uint32_t addr = bBase + (uint32_t)((ks + lrow) * BS_NT + wn + nj * 16 + lcol8) * 2;
                    ldsm_x4_t(r, addr);
                    b[nj * 2][0] = r[0]; b[nj * 2][1] = r[1];
                    b[nj * 2 + 1][0] = r[2]; b[nj * 2 + 1][1] = r[3];
                }
            }
#pragma unroll
            for (int mi = 0; mi < MI; mi++)
#pragma unroll
                for (int ni = 0; ni < 4; ni++)
                    mma16816(acc[mi][ni], a[mi], b[ni]);
        };

        computeK(0);

        const int nt = t + STAGES - 1;
        if (nt < nTiles) loadStage(nt, nt % STAGES);
        cp_commit();

        computeK(16);
        computeK(32);
        computeK(48);
    }

    // ---------------- epilogue ----------------
    float invr[MI][2];
    if constexpr (NORM) {
#pragma unroll
        for (int mi = 0; mi < MI; mi++)
#pragma unroll
            for (int hr = 0; hr < 2; hr++)
                invr[mi][hr] = 1.0f / rowsum[row0 + wm + mi * 16 + g + hr * 8];
    }

#pragma unroll
    for (int mi = 0; mi < MI; mi++) {
#pragma unroll
        for (int ni = 0; ni < 4; ni++) {
            const int r = row0 + wm + mi * 16 + g;
            const int cn = col0 + wn + ni * 8 + t4 * 2;
            if constexpr (EXPOUT) {
#pragma unroll
                for (int hr = 0; hr < 2; hr++) {
                    const int rr = r + hr * 8;
                    const float e0 = fast_exp(acc[mi][ni][hr * 2]);
                    const float e1 = fast_exp(acc[mi][ni][hr * 2 + 1]);
                    *(__half2*)(Ch + (size_t)rr * ldc + cn) = __floats2half2_rn(e0, e1);
                }
            } else if constexpr (OUT_HALF) {
#pragma unroll
                for (int hr = 0; hr < 2; hr++) {
                    const int rr = r + hr * 8;
                    float v0 = acc[mi][ni][hr * 2];
                    float v1 = acc[mi][ni][hr * 2 + 1];
                    if constexpr (HAS_BIAS) { v0 += bias[cn]; v1 += bias[cn + 1]; }
                    if constexpr (NORM) { v0 *= invr[mi][hr]; v1 *= invr[mi][hr]; }
                    else                { v0 *= aScale;       v1 *= aScale; }
                    *(__half2*)(Ch + (size_t)rr * ldc + cn) = __floats2half2_rn(v0, v1);
                }
            } else {
#pragma unroll
                for (int q = 0; q < 4; q++) {
                    const int rr = r + (q >> 1) * 8;
                    const int cc = cn + (q & 1);
                    if (cc < N) {
                        float bv = 0.f;
                        if constexpr (HAS_BIAS) bv = bias[cc];
                        Cf[(size_t)rr * ldc + cc] = (acc[mi][ni][q] + bv) * aScale;
                    }
                }
            }
        }
    }
}

// ---------------- row-sum of exp-scores (deterministic) -----------------------
__global__ __launch_bounds__(256) void rowsum_kernel(
    const __half2* __restrict__ E_, float* __restrict__ rs)
{
    __shared__ float red[8];
    const int row = blockIdx.x;
    const __half2* e = E_ + (size_t)row * (SEQ / 2);
    const int tid = threadIdx.x;

    float s = 0.f;
#pragma unroll
    for (int j = 0; j < 4; j++) {
        const float2 v = __half22float2(e[tid + j * 256]);
        s += v.x + v.y;
    }
#pragma unroll
    for (int o = 16; o; o >>= 1) s += __shfl_xor_sync(0xffffffffu, s, o);
    if ((tid & 31) == 0) red[tid >> 5] = s;
    __syncthreads();
    if (tid == 0) {
        float tot = 0.f;
#pragma unroll
        for (int i = 0; i < 8; i++) tot += red[i];
        rs[row] = tot;
    }
}

// ---------------- launch ------------------------------------------------------
extern "C" void kernel_launch(void* const* d_in, const int* in_sizes, int n_in,
                              void* d_out, int out_size)
{
    const float* x  = (const float*)d_in[0];
    const float* Wq = (const float*)d_in[1];
    const float* bq = (const float*)d_in[2];
    const float* Wk = (const float*)d_in[3];
    const float* bk = (const float*)d_in[4];
    const float* Wv = (const float*)d_in[5];
    const float* bv = (const float*)d_in[6];
    const float* Wo = (const float*)d_in[7];
    const float* bo = (const float*)d_in[8];
    float* out = (float*)d_out;

    __half *pxh, *pWqh, *pWkh, *pWvh, *pWoh, *pQ, *pK, *pV, *pAttn, *pCtx;
    float* pRS;
    cudaGetSymbolAddress((void**)&pxh, g_xh);
    cudaGetSymbolAddress((void**)&pWqh, g_Wqh);
    cudaGetSymbolAddress((void**)&pWkh, g_Wkh);
    cudaGetSymbolAddress((void**)&pWvh, g_Wvh);
    cudaGetSymbolAddress((void**)&pWoh, g_Woh);
    cudaGetSymbolAddress((void**)&pQ, g_Q);
    cudaGetSymbolAddress((void**)&pK, g_Km);
    cudaGetSymbolAddress((void**)&pV, g_V);
    cudaGetSymbolAddress((void**)&pAttn, g_attn);
    cudaGetSymbolAddress((void**)&pRS, g_rowsum);
    cudaGetSymbolAddress((void**)&pCtx, g_ctx);

    auto kQKV = gemm2<false, true, true, true, false, false, false, false>;
    auto kScores = gemm2<true, true, false, false, false, true, false, false>;
    auto kCtx = gemm2<false, true, false, false, true, false, true, false>;
    auto kOut = gemm2<false, false, true, false, false, false, false, true>;

    cudaFuncSetAttribute(kQKV, cudaFuncAttributeMaxDynamicSharedMemorySize, SMEM_BYTES);
    cudaFuncSetAttribute(kScores, cudaFuncAttributeMaxDynamicSharedMemorySize, SMEM_BYTES);
    cudaFuncSetAttribute(kCtx, cudaFuncAttributeMaxDynamicSharedMemorySize, SMEM_BYTES_N);
    cudaFuncSetAttribute(kOut, cudaFuncAttributeMaxDynamicSharedMemorySize, SMEM_BYTES);

    const float scale = 0.03608439182435161f;  // 1/sqrt(768)

    // fp32 -> fp16 with padding (MLP-boosted conversions)
    {
        const int gx = (KPAD / 2 + 1023) / 1024;   // 4 half2 per thread
        cvt_pad2d<<<dim3(gx, SEQ), 256>>>(x, (__half2*)pxh, VOC, KPAD / 2);
    }
    {
        const long nValid4 = ((long)VOC * EMB) / 4;
        const long nTot4 = ((long)KPAD * EMB) / 4;
        cvt_tail4<<<2048, 256>>>((const float4*)Wq, (uint2*)pWqh, nValid4, nTot4);
        cvt_tail4<<<2048, 256>>>((const float4*)Wk, (uint2*)pWkh, nValid4, nTot4);
        cvt_tail4<<<2048, 256>>>((const float4*)Wv, (uint2*)pWvh, nValid4, nTot4);
    }
    {
        const int gx = (NPAD / 2 + 1023) / 1024;
        cvt_pad2d<<<dim3(gx, EMB), 256>>>(Wo, (__half2*)pWoh, VOC, NPAD / 2);
    }

    // fused QKV projections (K = KPAD; pad rows zero). Q gets 1/sqrt(d) folded in.
    kQKV<<<dim3(18, 16), THREADS, SMEM_BYTES>>>(
        pxh, pWqh, pWkh, pWvh, bq, bk, bv,
        nullptr, pQ, pK, pV, nullptr,
        SEQ, EMB, KPAD, KPAD, EMB, EMB, scale);

    // expS = exp(Qs @ K^T)  (fp16, unnormalized)
    kScores<<<dim3(16, 16), THREADS, SMEM_BYTES>>>(
        pQ, pK, nullptr, nullptr, nullptr, nullptr, nullptr,
        nullptr, pAttn, nullptr, nullptr, nullptr,
        SEQ, SEQ, EMB, EMB, EMB, SEQ, 1.0f);

    // rowsum[r] = sum_k expS[r][k]
    rowsum_kernel<<<SEQ, 256>>>((const __half2*)pAttn, pRS);

    // ctx = (expS @ V) / rowsum   (narrow BN=64: 192 CTAs)
    kCtx<<<dim3(12, 16), THREADS, SMEM_BYTES_N>>>(
        pAttn, pV, nullptr, nullptr, nullptr, nullptr, nullptr,
        nullptr, pCtx, nullptr, nullptr, pRS,
        SEQ, EMB, SEQ, SEQ, EMB, EMB, 1.0f);

    // out = ctx @ Wo + bo   (GRIDT: row-block fastest -> Wo reused 16x per wave via L2)
    kOut<<<dim3(16, NPAD / BN), THREADS, SMEM_BYTES>>>(
        pCtx, pWoh, nullptr, nullptr, bo, nullptr, nullptr,
        out, nullptr, nullptr, nullptr, nullptr,
        SEQ, VOC, EMB, EMB, NPAD, VOC, 1.0f);
}

// round 16
// speedup vs baseline: 2.4620x; 1.0099x over previous
#include <cuda_runtime.h>
#include <cuda_fp16.h>
#include <stdint.h>

static constexpr int SEQ  = 2048;
static constexpr int VOC  = 50257;
static constexpr int EMB  = 768;
static constexpr int KPAD = 50304;   // VOC padded to multiple of 64 (K of QKV gemm)
static constexpr int NPAD = 50304;   // VOC padded to multiple of 128 (N of out gemm)

#define BM 128
#define BN 128
#define BK 64
#define STAGES 3
#define THREADS 256
#define A_STRIDE 72                       // 64+8 halfs -> 144B rows, ldsm conflict-free
#define BNT_STRIDE 136                    // non-BT wide B rows: 128+8 halfs
#define BNT_STRIDE_N 72                   // non-BT narrow B rows: 64+8 halfs
#define A_HALF_PER_STAGE (BM * A_STRIDE)  // 9216
#define B_HALF_WIDE (BM * A_STRIDE)       // 9216 (>= 64*136 = 8704)
#define B_HALF_NARROW (64 * BNT_STRIDE_N) // 4608
#define SMEM_BYTES  (STAGES * (A_HALF_PER_STAGE + B_HALF_WIDE) * 2)     // 110592
#define SMEM_BYTES_N (STAGES * (A_HALF_PER_STAGE + B_HALF_NARROW) * 2)  // 82944

// ---------------- scratch (__device__ globals; no allocation allowed) ---------
__device__ __half g_xh[(size_t)SEQ * KPAD];
__device__ __half g_Wqh[(size_t)KPAD * EMB];
__device__ __half g_Wkh[(size_t)KPAD * EMB];
__device__ __half g_Wvh[(size_t)KPAD * EMB];
__device__ __half g_Woh[(size_t)EMB * NPAD];
__device__ __half g_Q[SEQ * EMB];
__device__ __half g_Km[SEQ * EMB];
__device__ __half g_V[SEQ * EMB];
__device__ __half g_attn[(size_t)SEQ * SEQ];   // exp(scores), unnormalized
__device__ float  g_rowsum[SEQ];
__device__ __half g_ctx[SEQ * EMB];

// ---------------- helpers ----------------------------------------------------
__device__ __forceinline__ void cp_async16(uint32_t dst, const void* src) {
    asm volatile("cp.async.cg.shared.global [%0], [%1], 16;\n" :: "r"(dst), "l"(src));
}
__device__ __forceinline__ void cp_commit() {
    asm volatile("cp.async.commit_group;\n");
}
__device__ __forceinline__ void cp_wait() {
    asm volatile("cp.async.wait_group %0;\n" :: "n"(STAGES - 2));
}
__device__ __forceinline__ void ldsm_x4(uint32_t* r, uint32_t addr) {
    asm volatile("ldmatrix.sync.aligned.m8n8.x4.shared.b16 {%0,%1,%2,%3}, [%4];\n"
                 : "=r"(r[0]), "=r"(r[1]), "=r"(r[2]), "=r"(r[3]) : "r"(addr));
}
__device__ __forceinline__ void ldsm_x4_t(uint32_t* r, uint32_t addr) {
    asm volatile("ldmatrix.sync.aligned.m8n8.x4.trans.shared.b16 {%0,%1,%2,%3}, [%4];\n"
                 : "=r"(r[0]), "=r"(r[1]), "=r"(r[2]), "=r"(r[3]) : "r"(addr));
}
__device__ __forceinline__ void mma16816(float* c, const uint32_t* a, const uint32_t* b) {
    asm volatile(
        "mma.sync.aligned.m16n8k16.row.col.f32.f16.f16.f32 "
        "{%0,%1,%2,%3}, {%4,%5,%6,%7}, {%8,%9}, {%0,%1,%2,%3};\n"
        : "+f"(c[0]), "+f"(c[1]), "+f"(c[2]), "+f"(c[3])
        : "r"(a[0]), "r"(a[1]), "r"(a[2]), "r"(a[3]), "r"(b[0]), "r"(b[1]));
}
// Fast exp on the FMA pipe (no MUFU); valid for |score| within clamp range.
__device__ __forceinline__ float fast_exp(float x) {
    float y = x * 1.4426950408889634f;
    y = fminf(fmaxf(y, -100.0f), 15.5f);
    const float t = y + 12582912.0f;      // 1.5 * 2^23
    const float nf = t - 12582912.0f;
    const float f = y - nf;
    const int n = (int)nf;
    float p = 0.00133335581f;
    p = fmaf(p, f, 0.00961812910f);
    p = fmaf(p, f, 0.0555041086f);
    p = fmaf(p, f, 0.240226507f);
    p = fmaf(p, f, 0.693147182f);
    p = fmaf(p, f, 1.0f);
    return p * __int_as_float((n + 127) << 23);
}

// ---------------- conversion kernels ------------------------------------------
// Row-padded convert: 4 half2 outputs per thread (8 scalar LDGs in flight),
// uint4 fast-path store (dstW2 divisible by 4 -> 16B-aligned groups).
__global__ __launch_bounds__(256) void cvt_pad2d(const float* __restrict__ s,
                                                 __half2* __restrict__ d,
                                                 int srcW, int dstW2) {
    const int c2base = (blockIdx.x * 256 + threadIdx.x) * 4;
    const size_t row = blockIdx.y;
    if (c2base >= dstW2) return;
    const float* sr = s + row * (size_t)srcW;
    __half2* dr = d + row * (size_t)dstW2;

    const int colLast = (c2base + 3) * 2 + 1;
    if (colLast < srcW) {
        float v[8];
#pragma unroll
        for (int j = 0; j < 8; j++) v[j] = sr[c2base * 2 + j];
        uint4 o;
        __half2 h0 = __floats2half2_rn(v[0], v[1]);
        __half2 h1 = __floats2half2_rn(v[2], v[3]);
        __half2 h2 = __floats2half2_rn(v[4], v[5]);
        __half2 h3 = __floats2half2_rn(v[6], v[7]);
        o.x = *(uint32_t*)&h0; o.y = *(uint32_t*)&h1;
        o.z = *(uint32_t*)&h2; o.w = *(uint32_t*)&h3;
        *(uint4*)(dr + c2base) = o;
    } else {
#pragma unroll
        for (int u = 0; u < 4; u++) {
            const int c2 = c2base + u;
            if (c2 < dstW2) {
                const int col = c2 * 2;
                const float v0 = (col < srcW) ? sr[col] : 0.f;
                const float v1 = (col + 1 < srcW) ? sr[col + 1] : 0.f;
                dr[c2] = __floats2half2_rn(v0, v1);
            }
        }
    }
}
// Contiguous convert with zero tail (proven R14 shape), fused over 3 matrices:
// blockIdx.y selects (src, dst) pair. Keeps DRAM saturated across what were
// three separate launch ramps.
__global__ __launch_bounds__(256) void cvt_tail4_x3(
    const float4* __restrict__ s0, uint2* __restrict__ d0,
    const float4* __restrict__ s1, uint2* __restrict__ d1,
    const float4* __restrict__ s2, uint2* __restrict__ d2,
    long nValid4, long nTotal4) {
    const float4* s = (blockIdx.y == 0) ? s0 : (blockIdx.y == 1 ? s1 : s2);
    uint2* d = (blockIdx.y == 0) ? d0 : (blockIdx.y == 1 ? d1 : d2);
    long i = (long)blockIdx.x * blockDim.x + threadIdx.x;
    const long stride = (long)gridDim.x * blockDim.x;
    for (; i < nTotal4; i += stride) {
        float4 v = (i < nValid4) ? s[i] : make_float4(0.f, 0.f, 0.f, 0.f);
        __half2 lo = __floats2half2_rn(v.x, v.y);
        __half2 hi = __floats2half2_rn(v.z, v.w);
        uint2 o;
        o.x = *(const uint32_t*)&lo;
        o.y = *(const uint32_t*)&hi;
        d[i] = o;
    }
}

// ---------------- pipelined fp16 GEMM (BK=64, 3 stages, 2 CTA/SM) -------------
// C[M,N] = A[M,K] @ B (+bias)*alpha.  B row-major [K,N] if !BT, [N,K] if BT.
// NARROW: BN=64.  EXPOUT: write fp16 exp(acc), no guards.
// NORM: multiply by 1/rowsum[row] in epilogue.  GRIDT: row-block on blockIdx.x.
template <bool BT, bool OUT_HALF, bool HAS_BIAS, bool FUSED3, bool NARROW,
          bool EXPOUT, bool NORM, bool GRIDT>
__global__ __launch_bounds__(THREADS, 2) void gemm2(
    const __half* __restrict__ A,
    const __half* __restrict__ B0, const __half* __restrict__ B1, const __half* __restrict__ B2,
    const float* __restrict__ bias0, const float* __restrict__ bias1, const float* __restrict__ bias2,
    float* __restrict__ Cf,
    __half* __restrict__ Ch0, __half* __restrict__ Ch1, __half* __restrict__ Ch2,
    const float* __restrict__ rowsum,
    int M, int N, int K, int lda, int ldb, int ldc, float alpha)
{
    constexpr int BN_E = NARROW ? 64 : 128;
    constexpr int MI = NARROW ? 2 : 4;
    constexpr int B_HALF_STG = NARROW ? B_HALF_NARROW : B_HALF_WIDE;
    constexpr int BS_NT = NARROW ? BNT_STRIDE_N : BNT_STRIDE;

    extern __shared__ __half sm[];
    __half* As = sm;
    __half* Bs = sm + STAGES * A_HALF_PER_STAGE;

    const int tid = threadIdx.x;
    const int row0 = (GRIDT ? blockIdx.x : blockIdx.y) * BM;

    const __half* B = B0;
    const float* bias = bias0;
    __half* Ch = Ch0;
    float aScale = alpha;
    int col0;
    if constexpr (FUSED3) {
        const int blocksPer = N / BN_E;
        const int sel = blockIdx.x / blocksPer;
        col0 = (blockIdx.x % blocksPer) * BN_E;
        if (sel == 1) { B = B1; bias = bias1; Ch = Ch1; aScale = 1.f; }
        else if (sel == 2) { B = B2; bias = bias2; Ch = Ch2; aScale = 1.f; }
    } else {
        col0 = (GRIDT ? blockIdx.y : blockIdx.x) * BN_E;
    }

    const uint32_t smA = (uint32_t)__cvta_generic_to_shared(As);
    const uint32_t smB = (uint32_t)__cvta_generic_to_shared(Bs);

    const int nTiles = K / BK;

    auto loadStage = [&](int t, int slot) {
        const int k0 = t * BK;
#pragma unroll
        for (int h = 0; h < 4; h++) {
            const int c = tid + h * 256;
            const int row = c >> 3, kc = (c & 7) * 8;
            const uint32_t dst = smA + (uint32_t)(slot * A_HALF_PER_STAGE + row * A_STRIDE + kc) * 2;
            cp_async16(dst, A + (size_t)(row0 + row) * lda + (k0 + kc));
        }
        if constexpr (BT) {
#pragma unroll
            for (int h = 0; h < 4; h++) {
                const int c = tid + h * 256;
                const int nr = c >> 3, kc = (c & 7) * 8;
                const uint32_t dst = smB + (uint32_t)(slot * B_HALF_STG + nr * A_STRIDE + kc) * 2;
                cp_async16(dst, B + (size_t)(col0 + nr) * ldb + (k0 + kc));
            }
        } else if constexpr (NARROW) {
#pragma unroll
            for (int h = 0; h < 2; h++) {
                const int c = tid + h * 256;
                const int kr = c >> 3, nc = (c & 7) * 8;
                const uint32_t dst = smB + (uint32_t)(slot * B_HALF_STG + kr * BS_NT + nc) * 2;
                cp_async16(dst, B + (size_t)(k0 + kr) * ldb + (col0 + nc));
            }
        } else {
#pragma unroll
            for (int h = 0; h < 4; h++) {
                const int c = tid + h * 256;
                const int kr = c >> 4, nc = (c & 15) * 8;
                const uint32_t dst = smB + (uint32_t)(slot * B_HALF_STG + kr * BS_NT + nc) * 2;
                cp_async16(dst, B + (size_t)(k0 + kr) * ldb + (col0 + nc));
            }
        }
    };

    const int warp = tid >> 5, lane = tid & 31;
    const int wm = NARROW ? (warp & 3) * 32 : (warp & 1) * 64;
    const int wn = NARROW ? (warp >> 2) * 32 : (warp >> 1) * 32;
    const int g = lane >> 2, t4 = lane & 3;
    const int lrow = lane & 15;
    const int lcol8 = (lane >> 4) << 3;
    const int mrow = lane & 7;
    const int msel = lane >> 3;

    float acc[MI][4][4];
#pragma unroll
    for (int mi = 0; mi < MI; mi++)
#pragma unroll
        for (int ni = 0; ni < 4; ni++)
#pragma unroll
            for (int q = 0; q < 4; q++) acc[mi][ni][q] = 0.f;

#pragma unroll
    for (int s = 0; s < STAGES - 1; s++) {
        loadStage(s, s);
        cp_commit();
    }

    for (int t = 0; t < nTiles; t++) {
        cp_wait();
        __syncthreads();

        const int slot = t % STAGES;
        const uint32_t aBase = smA + (uint32_t)(slot * A_HALF_PER_STAGE) * 2;
        const uint32_t bBase = smB + (uint32_t)(slot * B_HALF_STG) * 2;

        auto computeK = [&](int ks) {
            uint32_t a[MI][4];
#pragma unroll
            for (int mi = 0; mi < MI; mi++) {
                const uint32_t addr = aBase + (uint32_t)((wm + mi * 16 + lrow) * A_STRIDE + ks + lcol8) * 2;
                ldsm_x4(a[mi], addr);
            }
            uint32_t b[4][2];
            if constexpr (BT) {
#pragma unroll
                for (int nj = 0; nj < 2; nj++) {
                    uint32_t r[4];
                    const int n = wn + nj * 16 + ((msel >> 1) << 3) + mrow;
                    const int kk = ks + ((msel & 1) << 3);
                    ldsm_x4(r, bBase + (uint32_t)(n * A_STRIDE + kk) * 2);
                    b[nj * 2][0] = r[0]; b[nj * 2][1] = r[1];
                    b[nj * 2 + 1][0] = r[2]; b[nj * 2 + 1][1] = r[3];
                }
            } else {
#pragma unroll
                for (int nj = 0; nj < 2; nj++) {
                    uint32_t r[4];
                    const uint32_t addr = bBase + (uint32_t)((ks + lrow) * BS_NT + wn + nj * 16 + lcol8) * 2;
                    ldsm_x4_t(r, addr);
                    b[nj * 2][0] = r[0]; b[nj * 2][1] = r[1];
                    b[nj * 2 + 1][0] = r[2]; b[nj * 2 + 1][1] = r[3];
                }
            }
#pragma unroll
            for (int mi = 0; mi < MI; mi++)
#pragma unroll
                for (int ni = 0; ni < 4; ni++)
                    mma16816(acc[mi][ni], a[mi], b[ni]);
        };

        computeK(0);

        const int nt = t + STAGES - 1;
        if (nt < nTiles) loadStage(nt, nt % STAGES);
        cp_commit();

        computeK(16);
        computeK(32);
        computeK(48);
    }

    // ---------------- epilogue ----------------
    float invr[MI][2];
    if constexpr (NORM) {
#pragma unroll
        for (int mi = 0; mi < MI; mi++)
#pragma unroll
            for (int hr = 0; hr < 2; hr++)
                invr[mi][hr] = 1.0f / rowsum[row0 + wm + mi * 16 + g + hr * 8];
    }

#pragma unroll
    for (int mi = 0; mi < MI; mi++) {
#pragma unroll
        for (int ni = 0; ni < 4; ni++) {
            const int r = row0 + wm + mi * 16 + g;
            const int cn = col0 + wn + ni * 8 + t4 * 2;
            if constexpr (EXPOUT) {
#pragma unroll
                for (int hr = 0; hr < 2; hr++) {
                    const int rr = r + hr * 8;
                    const float e0 = fast_exp(acc[mi][ni][hr * 2]);
                    const float e1 = fast_exp(acc[mi][ni][hr * 2 + 1]);
                    *(__half2*)(Ch + (size_t)rr * ldc + cn) = __floats2half2_rn(e0, e1);
                }
            } else if constexpr (OUT_HALF) {
#pragma unroll
                for (int hr = 0; hr < 2; hr++) {
                    const int rr = r + hr * 8;
                    float v0 = acc[mi][ni][hr * 2];
                    float v1 = acc[mi][ni][hr * 2 + 1];
                    if constexpr (HAS_BIAS) { v0 += bias[cn]; v1 += bias[cn + 1]; }
                    if constexpr (NORM) { v0 *= invr[mi][hr]; v1 *= invr[mi][hr]; }
                    else                { v0 *= aScale;       v1 *= aScale; }
                    *(__half2*)(Ch + (size_t)rr * ldc + cn) = __floats2half2_rn(v0, v1);
                }
            } else {
#pragma unroll
                for (int q = 0; q < 4; q++) {
                    const int rr = r + (q >> 1) * 8;
                    const int cc = cn + (q & 1);
                    if (cc < N) {
                        float bv = 0.f;
                        if constexpr (HAS_BIAS) bv = bias[cc];
                        Cf[(size_t)rr * ldc + cc] = (acc[mi][ni][q] + bv) * aScale;
                    }
                }
            }
        }
    }
}

// ---------------- row-sum of exp-scores (deterministic) -----------------------
__global__ __launch_bounds__(256) void rowsum_kernel(
    const __half2* __restrict__ E_, float* __restrict__ rs)
{
    __shared__ float red[8];
    const int row = blockIdx.x;
    const __half2* e = E_ + (size_t)row * (SEQ / 2);
    const int tid = threadIdx.x;

    float s = 0.f;
#pragma unroll
    for (int j = 0; j < 4; j++) {
        const float2 v = __half22float2(e[tid + j * 256]);
        s += v.x + v.y;
    }
#pragma unroll
    for (int o = 16; o; o >>= 1) s += __shfl_xor_sync(0xffffffffu, s, o);
    if ((tid & 31) == 0) red[tid >> 5] = s;
    __syncthreads();
    if (tid == 0) {
        float tot = 0.f;
#pragma unroll
        for (int i = 0; i < 8; i++) tot += red[i];
        rs[row] = tot;
    }
}

// ---------------- launch ------------------------------------------------------
extern "C" void kernel_launch(void* const* d_in, const int* in_sizes, int n_in,
                              void* d_out, int out_size)
{
    const float* x  = (const float*)d_in[0];
    const float* Wq = (const float*)d_in[1];
    const float* bq = (const float*)d_in[2];
    const float* Wk = (const float*)d_in[3];
    const float* bk = (const float*)d_in[4];
    const float* Wv = (const float*)d_in[5];
    const float* bv = (const float*)d_in[6];
    const float* Wo = (const float*)d_in[7];
    const float* bo = (const float*)d_in[8];
    float* out = (float*)d_out;

    __half *pxh, *pWqh, *pWkh, *pWvh, *pWoh, *pQ, *pK, *pV, *pAttn, *pCtx;
    float* pRS;
    cudaGetSymbolAddress((void**)&pxh, g_xh);
    cudaGetSymbolAddress((void**)&pWqh, g_Wqh);
    cudaGetSymbolAddress((void**)&pWkh, g_Wkh);
    cudaGetSymbolAddress((void**)&pWvh, g_Wvh);
    cudaGetSymbolAddress((void**)&pWoh, g_Woh);
    cudaGetSymbolAddress((void**)&pQ, g_Q);
    cudaGetSymbolAddress((void**)&pK, g_Km);
    cudaGetSymbolAddress((void**)&pV, g_V);
    cudaGetSymbolAddress((void**)&pAttn, g_attn);
    cudaGetSymbolAddress((void**)&pRS, g_rowsum);
    cudaGetSymbolAddress((void**)&pCtx, g_ctx);

    auto kQKV = gemm2<false, true, true, true, false, false, false, false>;
    auto kScores = gemm2<true, true, false, false, false, true, false, false>;
    auto kCtx = gemm2<false, true, false, false, true, false, true, false>;
    auto kOut = gemm2<false, false, true, false, false, false, false, true>;

    cudaFuncSetAttribute(kQKV, cudaFuncAttributeMaxDynamicSharedMemorySize, SMEM_BYTES);
    cudaFuncSetAttribute(kScores, cudaFuncAttributeMaxDynamicSharedMemorySize, SMEM_BYTES);
    cudaFuncSetAttribute(kCtx, cudaFuncAttributeMaxDynamicSharedMemorySize, SMEM_BYTES_N);
    cudaFuncSetAttribute(kOut, cudaFuncAttributeMaxDynamicSharedMemorySize, SMEM_BYTES);

    const float scale = 0.03608439182435161f;  // 1/sqrt(768)

    // fp32 -> fp16 with padding
    {
        const int gx = (KPAD / 2 + 1023) / 1024;   // 4 half2 per thread
        cvt_pad2d<<<dim3(gx, SEQ), 256>>>(x, (__half2*)pxh, VOC, KPAD / 2);
    }
    {
        const long nValid4 = ((long)VOC * EMB) / 4;
        const long nTot4 = ((long)KPAD * EMB) / 4;
        cvt_tail4_x3<<<dim3(2731, 3), 256>>>(
            (const float4*)Wq, (uint2*)pWqh,
            (const float4*)Wk, (uint2*)pWkh,
            (const float4*)Wv, (uint2*)pWvh,
            nValid4, nTot4);
    }
    {
        const int gx = (NPAD / 2 + 1023) / 1024;
        cvt_pad2d<<<dim3(gx, EMB), 256>>>(Wo, (__half2*)pWoh, VOC, NPAD / 2);
    }

    // fused QKV projections (K = KPAD; pad rows zero). Q gets 1/sqrt(d) folded in.
    kQKV<<<dim3(18, 16), THREADS, SMEM_BYTES>>>(
        pxh, pWqh, pWkh, pWvh, bq, bk, bv,
        nullptr, pQ, pK, pV, nullptr,
        SEQ, EMB, KPAD, KPAD, EMB, EMB, scale);

    // expS = exp(Qs @ K^T)  (fp16, unnormalized)
    kScores<<<dim3(16, 16), THREADS, SMEM_BYTES>>>(
        pQ, pK, nullptr, nullptr, nullptr, nullptr, nullptr,
        nullptr, pAttn, nullptr, nullptr, nullptr,
        SEQ, SEQ, EMB, EMB, EMB, SEQ, 1.0f);

    // rowsum[r] = sum_k expS[r][k]
    rowsum_kernel<<<SEQ, 256>>>((const __half2*)pAttn, pRS);

    // ctx = (expS @ V) / rowsum   (narrow BN=64: 192 CTAs)
    kCtx<<<dim3(12, 16), THREADS, SMEM_BYTES_N>>>(
        pAttn, pV, nullptr, nullptr, nullptr, nullptr, nullptr,
        nullptr, pCtx, nullptr, nullptr, pRS,
        SEQ, EMB, SEQ, SEQ, EMB, EMB, 1.0f);

    // out = ctx @ Wo + bo   (GRIDT: row-block fastest -> Wo reused 16x per wave via L2)
    kOut<<<dim3(16, NPAD / BN), THREADS, SMEM_BYTES>>>(
        pCtx, pWoh, nullptr, nullptr, bo, nullptr, nullptr,
        out, nullptr, nullptr, nullptr, nullptr,
        SEQ, VOC, EMB, EMB, NPAD, VOC, 1.0f);
}